// round 3
// baseline (speedup 1.0000x reference)
#include <cuda_runtime.h>
#include <cstdint>

// ---------------------------------------------------------------------------
// TriXLinear (sm_103 baseline-PTX version: tcgen05 unavailable in this build;
// tensor path = mma.sync m16n8k32.s8).
//
//   out = (x @ sign(W)^T) * scales * gate_mask
//
// Scheme:
//   x = S1*q1 + (S1/254)*q2   (int8 two-level; exact +-1 weights)
//   out_fp = (S1/254) * (254*acc_q1 + acc_q2) * scales[col], gated rows only.
// Gate skipping: per output tile t (1024 cols), compact gated rows, gather
// their q1/q2 rows into tiled SW-swizzled scratch, GEMM only those rows.
// GEMM: BM=128 BN=128 BK=128B, 4-stage cp.async.bulk + mbarrier pipeline.
// ---------------------------------------------------------------------------

#define MDIM 4096
#define NDIM 4096
#define KDIM 4096
#define S1   0.0625f                  // 2^-4, covers |x| <= 7.94
#define SC   (S1 / 254.0f)

#define BM 128
#define BN 128
#define BKB 128                        // K bytes per stage (int8)
#define NKT (KDIM / BKB)               // 32 k-stages
#define STAGES 4
#define STAGE_BYTES 49152              // Aq1 16K + Aq2 16K + B 16K
#define SMEM_SC 64                     // scales cache (128 f32) at byte 64
#define SMEM_ST 1024
#define SMEM_TOTAL (SMEM_ST + STAGES * STAGE_BYTES)   // 197632

// ------------------------------- scratch -----------------------------------
__device__ __align__(16)   int8_t g_q1[(size_t)MDIM * KDIM];
__device__ __align__(16)   int8_t g_q2[(size_t)MDIM * KDIM];
__device__ __align__(1024) unsigned char g_Wt[(size_t)16 * 1024 * 1024];
__device__ __align__(1024) unsigned char g_At[(size_t)128 * 1024 * 1024];
__device__ int g_cnt[4];
__device__ int g_rows[4][MDIM];

// ------------------------------ PTX helpers --------------------------------
__device__ __forceinline__ uint32_t smem_u32(const void* p) {
    uint32_t a;
    asm("{ .reg .u64 t; cvta.to.shared.u64 t, %1; cvt.u32.u64 %0, t; }"
        : "=r"(a) : "l"(p));
    return a;
}
__device__ __forceinline__ void mbar_init(uint32_t mb, uint32_t cnt) {
    asm volatile("mbarrier.init.shared.b64 [%0], %1;" :: "r"(mb), "r"(cnt) : "memory");
}
__device__ __forceinline__ void mbar_expect_tx(uint32_t mb, uint32_t bytes) {
    asm volatile("mbarrier.arrive.expect_tx.shared.b64 _, [%0], %1;"
                 :: "r"(mb), "r"(bytes) : "memory");
}
__device__ __forceinline__ void mbar_wait(uint32_t mb, uint32_t parity) {
    asm volatile(
        "{\n\t.reg .pred P;\n\t"
        "WL_%=:\n\t"
        "mbarrier.try_wait.parity.acquire.cta.shared::cta.b64 P, [%0], %1, 0x989680;\n\t"
        "@P bra.uni WD_%=;\n\t"
        "bra.uni WL_%=;\n\t"
        "WD_%=:\n\t}"
        :: "r"(mb), "r"(parity) : "memory");
}
__device__ __forceinline__ void bulk_g2s(uint32_t dst, const void* src,
                                         uint32_t bytes, uint32_t mb) {
    asm volatile(
        "cp.async.bulk.shared::cta.global.mbarrier::complete_tx::bytes "
        "[%0], [%1], %2, [%3];"
        :: "r"(dst), "l"(src), "r"(bytes), "r"(mb) : "memory");
}
__device__ __forceinline__ void ldm_x4(uint32_t* r, uint32_t addr) {
    asm volatile("ldmatrix.sync.aligned.m8n8.x4.shared.b16 {%0,%1,%2,%3}, [%4];"
                 : "=r"(r[0]), "=r"(r[1]), "=r"(r[2]), "=r"(r[3]) : "r"(addr));
}
__device__ __forceinline__ void imma(int* c, const uint32_t* a,
                                     uint32_t b0, uint32_t b1) {
    asm volatile(
        "mma.sync.aligned.m16n8k32.row.col.s32.s8.s8.s32 "
        "{%0,%1,%2,%3}, {%4,%5,%6,%7}, {%8,%9}, {%0,%1,%2,%3};"
        : "+r"(c[0]), "+r"(c[1]), "+r"(c[2]), "+r"(c[3])
        : "r"(a[0]), "r"(a[1]), "r"(a[2]), "r"(a[3]), "r"(b0), "r"(b1));
}

// ------------------------------ prep kernels --------------------------------

// zero ungated (row, tile) blocks of out (out is poisoned before timing)
__global__ void zero_ungated(const int* __restrict__ gate,
                             float* __restrict__ out) {
    int bid = blockIdx.x;            // 16384 = 4096 rows * 4 tiles
    int r = bid >> 2, t = bid & 3;
    if (gate[r * 4 + t] != 0) return;
    float4 z = {0.f, 0.f, 0.f, 0.f};
    reinterpret_cast<float4*>(out + (size_t)r * NDIM + t * 1024)[threadIdx.x] = z;
}

// two-level int8 quantization of x (row-major)
__global__ void quant_x(const float* __restrict__ x) {
    size_t i = ((size_t)blockIdx.x * blockDim.x + threadIdx.x) * 8;
    const float4* p = reinterpret_cast<const float4*>(x + i);
    float4 v0 = p[0], v1 = p[1];
    float f[8] = {v0.x, v0.y, v0.z, v0.w, v1.x, v1.y, v1.z, v1.w};
    signed char q1[8], q2[8];
#pragma unroll
    for (int j = 0; j < 8; j++) {
        float a = rintf(f[j] * (1.0f / S1));
        a = fminf(fmaxf(a, -127.f), 127.f);
        float r = f[j] - a * S1;
        float b = rintf(r * (254.0f / S1));
        b = fminf(fmaxf(b, -127.f), 127.f);
        q1[j] = (signed char)a;
        q2[j] = (signed char)b;
    }
    *reinterpret_cast<uint2*>(g_q1 + i) = *reinterpret_cast<uint2*>(q1);
    *reinterpret_cast<uint2*>(g_q2 + i) = *reinterpret_cast<uint2*>(q2);
}

// sign(W) -> int8, tiled [nb=row/128][kblk=k/128] 16KB chunks, swizzled:
// within chunk: row r (0..127) * 128B, 16B-chunk c stored at (c ^ (r&7)).
__global__ void sign_w(const float* __restrict__ w) {
    size_t idx = (size_t)blockIdx.x * blockDim.x + threadIdx.x;  // *8 elems
    int row = (int)(idx >> 9);
    int k0  = ((int)idx & 511) * 8;
    const float4* p = reinterpret_cast<const float4*>(w + (size_t)row * KDIM + k0);
    float4 v0 = p[0], v1 = p[1];
    float f[8] = {v0.x, v0.y, v0.z, v0.w, v1.x, v1.y, v1.z, v1.w};
    signed char s[8];
#pragma unroll
    for (int j = 0; j < 8; j++)
        s[j] = (f[j] > 0.f) ? 1 : ((f[j] < 0.f) ? -1 : 0);
    int nb = row >> 7, r = row & 127, kblk = k0 >> 7, kw = k0 & 127;
    int c = kw >> 4, inner = kw & 15;   // inner in {0, 8}
    size_t off = (((size_t)(nb * 32 + kblk)) << 14) +
                 (size_t)r * 128 + ((c ^ (r & 7)) << 4) + inner;
    *reinterpret_cast<uint2*>(g_Wt + off) = *reinterpret_cast<uint2*>(s);
}

// per-tile gated row compaction (single block; zeroes counters each launch)
__global__ void compact_gate(const int* __restrict__ gate) {
    if (threadIdx.x < 4) g_cnt[threadIdx.x] = 0;
    __syncthreads();
    for (int r = threadIdx.x; r < MDIM; r += blockDim.x) {
#pragma unroll
        for (int t = 0; t < 4; t++) {
            if (gate[r * 4 + t] != 0) {
                int pos = atomicAdd(&g_cnt[t], 1);
                g_rows[t][pos] = r;
            }
        }
    }
}

// gather gated q1/q2 rows into tiled+swizzled A scratch:
// chunk (t, mblk) = 1MB: [kblk 0..31][q1 16K | q2 16K], same swizzle as W.
__global__ __launch_bounds__(256) void gather_a() {
    int mblk = blockIdx.x, t = blockIdx.y;
    int cnt = g_cnt[t];
    if (mblk * 128 >= cnt) return;
    __shared__ int srow[128];
    int tid = threadIdx.x;
    if (tid < 128) {
        int gidx = mblk * 128 + tid;
        srow[tid] = (gidx < cnt) ? g_rows[t][gidx] : g_rows[t][0];
    }
    __syncthreads();
    size_t base = ((size_t)(t * 32 + mblk)) << 20;
    int r = tid >> 3, c = tid & 7;           // 32 rows x 8 chunks per pass
    size_t doff = (size_t)r * 128 + ((c ^ (r & 7)) << 4);
#pragma unroll 1
    for (int kblk = 0; kblk < 32; kblk++) {
        size_t db = base + (size_t)kblk * 32768;
#pragma unroll
        for (int rp = 0; rp < 4; rp++) {      // rows r, r+32, r+64, r+96
            int rr = r + rp * 32;
            size_t so = (size_t)srow[rr] * KDIM + kblk * 128 + c * 16;
            size_t dd = db + (size_t)rp * 32 * 128 + doff;
            *reinterpret_cast<uint4*>(g_At + dd) =
                *reinterpret_cast<const uint4*>(g_q1 + so);
            *reinterpret_cast<uint4*>(g_At + 16384 + dd) =
                *reinterpret_cast<const uint4*>(g_q2 + so);
        }
    }
}

// ------------------------------ GEMM kernel ---------------------------------
// grid (8 nblk, 32 mblk, 4 t), 256 threads, warp grid 4(M) x 2(N), warp 32x64.

__global__ __launch_bounds__(256, 1) void trix_imma(
    const float* __restrict__ scales,
    float* __restrict__ out) {
    const int t = blockIdx.z, mblk = blockIdx.y, nblk = blockIdx.x;
    const int cnt = g_cnt[t];
    if (mblk * 128 >= cnt) return;

    extern __shared__ char smem[];
    const uint32_t sb = smem_u32(smem);
    const int tid = threadIdx.x;
    const int warp = tid >> 5, lane = tid & 31;
    const int wm = warp & 3, wn = warp >> 2;
    const int n0 = t * 1024 + nblk * 128;
    const int nb = t * 8 + nblk;

    if (tid < 128)
        reinterpret_cast<float*>(smem + SMEM_SC)[tid] = scales[n0 + tid];
    if (tid == 0) {
#pragma unroll
        for (int s = 0; s < STAGES; s++) mbar_init(sb + 8u * s, 1);
    }
    __syncthreads();

    const unsigned char* aSrc = g_At + (((size_t)(t * 32 + mblk)) << 20);
    const unsigned char* bSrc = g_Wt + (((size_t)nb * 32) << 14);

    auto fill = [&](int s, int kt) {
        uint32_t mb = sb + 8u * s;
        uint32_t st = sb + SMEM_ST + s * STAGE_BYTES;
        mbar_expect_tx(mb, STAGE_BYTES);
        bulk_g2s(st,         aSrc + ((size_t)kt << 15), 32768, mb);
        bulk_g2s(st + 32768, bSrc + ((size_t)kt << 14), 16384, mb);
    };
    if (tid == 0) {
#pragma unroll
        for (int s = 0; s < STAGES; s++) fill(s, s);
    }

    // per-thread ldmatrix row/swizzle precompute
    int aR[2], bR[4];
#pragma unroll
    for (int ms = 0; ms < 2; ms++) aR[ms] = wm * 32 + ms * 16 + (lane & 15);
    const int aCadd = lane >> 4;
#pragma unroll
    for (int nq = 0; nq < 4; nq++)
        bR[nq] = wn * 64 + nq * 16 + (lane & 7) + ((lane >> 4) << 3);
    const int bCadd = (lane >> 3) & 1;

    int d1[2][8][4], d2[2][8][4];
#pragma unroll
    for (int a = 0; a < 2; a++)
#pragma unroll
        for (int b = 0; b < 8; b++)
#pragma unroll
            for (int c = 0; c < 4; c++) { d1[a][b][c] = 0; d2[a][b][c] = 0; }

    for (int kt = 0; kt < NKT; kt++) {
        const int s = kt & 3;
        mbar_wait(sb + 8u * s, (kt >> 2) & 1);
        const uint32_t st = sb + SMEM_ST + s * STAGE_BYTES;
#pragma unroll
        for (int ks = 0; ks < 4; ks++) {
            uint32_t a1[2][4], a2[2][4], bf[4][4];
#pragma unroll
            for (int ms = 0; ms < 2; ms++) {
                uint32_t off = aR[ms] * 128 +
                               (((ks * 2 + aCadd) ^ (aR[ms] & 7)) << 4);
                ldm_x4(a1[ms], st + off);
                ldm_x4(a2[ms], st + 16384 + off);
            }
#pragma unroll
            for (int nq = 0; nq < 4; nq++) {
                uint32_t off = bR[nq] * 128 +
                               (((ks * 2 + bCadd) ^ (bR[nq] & 7)) << 4);
                ldm_x4(bf[nq], st + 32768 + off);
            }
#pragma unroll
            for (int ms = 0; ms < 2; ms++)
#pragma unroll
                for (int nq = 0; nq < 4; nq++) {
                    imma(d1[ms][nq * 2],     a1[ms], bf[nq][0], bf[nq][1]);
                    imma(d1[ms][nq * 2 + 1], a1[ms], bf[nq][2], bf[nq][3]);
                    imma(d2[ms][nq * 2],     a2[ms], bf[nq][0], bf[nq][1]);
                    imma(d2[ms][nq * 2 + 1], a2[ms], bf[nq][2], bf[nq][3]);
                }
        }
        __syncthreads();
        if (tid == 0 && kt + STAGES < NKT) fill(s, kt + STAGES);
    }

    // epilogue: out = SC * (254*acc1 + acc2) * scales[col] (gated rows only)
    const float* sSc = reinterpret_cast<const float*>(smem + SMEM_SC);
#pragma unroll
    for (int ms = 0; ms < 2; ms++) {
#pragma unroll
        for (int half = 0; half < 2; half++) {
            int gidx = mblk * 128 + wm * 32 + ms * 16 + (lane >> 2) + half * 8;
            if (gidx >= cnt) continue;
            int row = g_rows[t][gidx];
            float* orow = out + (size_t)row * NDIM + n0;
#pragma unroll
            for (int ns = 0; ns < 8; ns++) {
                int col = wn * 64 + ns * 8 + (lane & 3) * 2;
                float2 v;
                v.x = SC * fmaf(254.f, (float)d1[ms][ns][half * 2],
                                (float)d2[ms][ns][half * 2]) * sSc[col];
                v.y = SC * fmaf(254.f, (float)d1[ms][ns][half * 2 + 1],
                                (float)d2[ms][ns][half * 2 + 1]) * sSc[col + 1];
                *reinterpret_cast<float2*>(orow + col) = v;
            }
        }
    }
}

// ------------------------------ launch --------------------------------------

extern "C" void kernel_launch(void* const* d_in, const int* in_sizes, int n_in,
                              void* d_out, int out_size) {
    const float* x      = (const float*)d_in[0];
    const int*   gate   = (const int*)d_in[1];
    const float* weight = (const float*)d_in[2];
    const float* scales = (const float*)d_in[3];
    float* out = (float*)d_out;

    cudaFuncSetAttribute(trix_imma,
                         cudaFuncAttributeMaxDynamicSharedMemorySize, SMEM_TOTAL);

    zero_ungated<<<MDIM * 4, 256>>>(gate, out);
    quant_x<<<(int)((size_t)MDIM * KDIM / 8 / 256), 256>>>(x);
    sign_w<<<(int)((size_t)NDIM * KDIM / 8 / 256), 256>>>(weight);
    compact_gate<<<1, 1024>>>(gate);
    gather_a<<<dim3(32, 4), 256>>>();
    trix_imma<<<dim3(8, 32, 4), 256, SMEM_TOTAL>>>(scales, out);
}

// round 4
// speedup vs baseline: 3.4394x; 3.4394x over previous
#include <cuda_runtime.h>
#include <cuda_fp16.h>
#include <cstdint>

// ---------------------------------------------------------------------------
// TriXLinear (sm_103 baseline PTX; tensor path = mma.sync m16n8k16 f16).
//   out = (x @ sign(W)^T) * scales * gate_mask
// Scheme: x -> fp16 (norm rel err ~2.1e-4), W -> +-1 fp16 (exact).
// Gate skipping: per tile t (1024 cols) compact gated rows, gather them into
// tiled SW-swizzled scratch, GEMM only those rows; ungated blocks zeroed.
// GEMM: BM=128 BN=128 BK=64, 4-stage cp.async.bulk + mbarrier pipeline.
// ---------------------------------------------------------------------------

#define MDIM 4096
#define NDIM 4096
#define KDIM 4096

#define NKT 64                         // k-stages (64 fp16 = 128B per row)
#define STAGES 4
#define STAGE_BYTES 32768              // A 16K + B 16K
#define SMEM_SC 64
#define SMEM_ST 1024
#define SMEM_TOTAL (SMEM_ST + STAGES * STAGE_BYTES)   // 132096

// ------------------------------- scratch -----------------------------------
__device__ __align__(16)   __half g_Xh[(size_t)MDIM * KDIM];          // 32MB
__device__ __align__(1024) unsigned char g_Wt[(size_t)32 * 1024 * 1024];
__device__ __align__(1024) unsigned char g_At[(size_t)128 * 1024 * 1024];
__device__ int g_cnt[4];
__device__ int g_rows[4][MDIM];

// ------------------------------ PTX helpers --------------------------------
__device__ __forceinline__ uint32_t smem_u32(const void* p) {
    uint32_t a;
    asm("{ .reg .u64 t; cvta.to.shared.u64 t, %1; cvt.u32.u64 %0, t; }"
        : "=r"(a) : "l"(p));
    return a;
}
__device__ __forceinline__ void mbar_init(uint32_t mb, uint32_t cnt) {
    asm volatile("mbarrier.init.shared.b64 [%0], %1;" :: "r"(mb), "r"(cnt) : "memory");
}
__device__ __forceinline__ void mbar_expect_tx(uint32_t mb, uint32_t bytes) {
    asm volatile("mbarrier.arrive.expect_tx.shared.b64 _, [%0], %1;"
                 :: "r"(mb), "r"(bytes) : "memory");
}
__device__ __forceinline__ void mbar_wait(uint32_t mb, uint32_t parity) {
    asm volatile(
        "{\n\t.reg .pred P;\n\t"
        "WL_%=:\n\t"
        "mbarrier.try_wait.parity.acquire.cta.shared::cta.b64 P, [%0], %1, 0x989680;\n\t"
        "@P bra.uni WD_%=;\n\t"
        "bra.uni WL_%=;\n\t"
        "WD_%=:\n\t}"
        :: "r"(mb), "r"(parity) : "memory");
}
__device__ __forceinline__ void bulk_g2s(uint32_t dst, const void* src,
                                         uint32_t bytes, uint32_t mb) {
    asm volatile(
        "cp.async.bulk.shared::cta.global.mbarrier::complete_tx::bytes "
        "[%0], [%1], %2, [%3];"
        :: "r"(dst), "l"(src), "r"(bytes), "r"(mb) : "memory");
}
__device__ __forceinline__ void ldm_x4(uint32_t* r, uint32_t addr) {
    asm volatile("ldmatrix.sync.aligned.m8n8.x4.shared.b16 {%0,%1,%2,%3}, [%4];"
                 : "=r"(r[0]), "=r"(r[1]), "=r"(r[2]), "=r"(r[3]) : "r"(addr));
}
__device__ __forceinline__ void hmma(float* c, const uint32_t* a,
                                     uint32_t b0, uint32_t b1) {
    asm volatile(
        "mma.sync.aligned.m16n8k16.row.col.f32.f16.f16.f32 "
        "{%0,%1,%2,%3}, {%4,%5,%6,%7}, {%8,%9}, {%0,%1,%2,%3};"
        : "+f"(c[0]), "+f"(c[1]), "+f"(c[2]), "+f"(c[3])
        : "r"(a[0]), "r"(a[1]), "r"(a[2]), "r"(a[3]), "r"(b0), "r"(b1));
}

// ------------------------------ prep kernels --------------------------------

// zero ungated (row, tile) output blocks; block 0 also zeroes g_cnt
__global__ void zero_ungated(const int* __restrict__ gate,
                             float* __restrict__ out) {
    int bid = blockIdx.x;            // 16384 = 4096 rows * 4 tiles
    if (bid == 0 && threadIdx.x < 4) g_cnt[threadIdx.x] = 0;
    int r = bid >> 2, t = bid & 3;
    if (gate[r * 4 + t] != 0) return;
    float4 z = {0.f, 0.f, 0.f, 0.f};
    reinterpret_cast<float4*>(out + (size_t)r * NDIM + t * 1024)[threadIdx.x] = z;
}

// x -> fp16 row-major
__global__ void quant_x(const float* __restrict__ x) {
    size_t i = ((size_t)blockIdx.x * blockDim.x + threadIdx.x) * 8;
    const float4* p = reinterpret_cast<const float4*>(x + i);
    float4 v0 = p[0], v1 = p[1];
    float f[8] = {v0.x, v0.y, v0.z, v0.w, v1.x, v1.y, v1.z, v1.w};
    __half h[8];
#pragma unroll
    for (int j = 0; j < 8; j++) h[j] = __float2half_rn(f[j]);
    *reinterpret_cast<uint4*>(g_Xh + i) = *reinterpret_cast<uint4*>(h);
}

// sign(W) -> fp16, tiled [nb][kblk] 16KB stages, swizzled 16B chunks:
// row r: chunk c stored at (c ^ (r&7)).
__global__ void sign_w(const float* __restrict__ w) {
    size_t idx = (size_t)blockIdx.x * blockDim.x + threadIdx.x;  // *8 elems
    int row = (int)(idx >> 9);
    int k0  = ((int)idx & 511) * 8;
    const float4* p = reinterpret_cast<const float4*>(w + (size_t)row * KDIM + k0);
    float4 v0 = p[0], v1 = p[1];
    float f[8] = {v0.x, v0.y, v0.z, v0.w, v1.x, v1.y, v1.z, v1.w};
    __half s[8];
#pragma unroll
    for (int j = 0; j < 8; j++)
        s[j] = __float2half_rn((f[j] > 0.f) ? 1.f : ((f[j] < 0.f) ? -1.f : 0.f));
    int nb = row >> 7, r = row & 127, kblk = k0 >> 6;
    int c = (k0 & 63) >> 3;                    // 16B chunk within 128B row
    size_t off = (((size_t)(nb * 64 + kblk)) << 14) +
                 (size_t)r * 128 + ((size_t)(c ^ (r & 7)) << 4);
    *reinterpret_cast<uint4*>(g_Wt + off) = *reinterpret_cast<uint4*>(s);
}

// gated row compaction, parallel (order within g_rows is irrelevant)
__global__ void compact_gate(const int* __restrict__ gate) {
    int r = blockIdx.x * blockDim.x + threadIdx.x;
    if (r >= MDIM) return;
#pragma unroll
    for (int t = 0; t < 4; t++) {
        if (gate[r * 4 + t] != 0) {
            int pos = atomicAdd(&g_cnt[t], 1);
            g_rows[t][pos] = r;
        }
    }
}

// gather gated fp16 rows into tiled+swizzled A scratch:
// chunk (t, mblk) = 1MB = [kblk 0..63] x 16KB stages, same swizzle as W.
__global__ __launch_bounds__(256) void gather_a() {
    int mblk = blockIdx.x, t = blockIdx.y;
    int cnt = g_cnt[t];
    if (mblk * 128 >= cnt) return;
    __shared__ int srow[128];
    int tid = threadIdx.x;
    if (tid < 128) {
        int gidx = mblk * 128 + tid;
        srow[tid] = (gidx < cnt) ? g_rows[t][gidx] : g_rows[t][0];
    }
    __syncthreads();
    size_t base = ((size_t)(t * 32 + mblk)) << 20;
    int r = tid >> 3, c = tid & 7;           // 32 rows x 8 chunks per pass
#pragma unroll 1
    for (int kblk = 0; kblk < 64; kblk++) {
        size_t db = base + ((size_t)kblk << 14);
#pragma unroll
        for (int rp = 0; rp < 4; rp++) {      // rows r, r+32, r+64, r+96
            int rr = r + rp * 32;
            size_t so = (size_t)srow[rr] * 8192 + (size_t)kblk * 128 + c * 16;
            size_t dd = db + (size_t)rr * 128 + ((size_t)(c ^ (rr & 7)) << 4);
            *reinterpret_cast<uint4*>(g_At + dd) =
                *reinterpret_cast<const uint4*>(
                    reinterpret_cast<const unsigned char*>(g_Xh) + so);
        }
    }
}

// ------------------------------ GEMM kernel ---------------------------------
// grid (8 nblk, 32 mblk, 4 t), 256 threads, warp grid 4(M) x 2(N), warp 32x64.

__global__ __launch_bounds__(256, 1) void trix_hmma(
    const float* __restrict__ scales,
    float* __restrict__ out) {
    const int t = blockIdx.z, mblk = blockIdx.y, nblk = blockIdx.x;
    const int cnt = g_cnt[t];
    if (mblk * 128 >= cnt) return;

    extern __shared__ char smem[];
    const uint32_t sb = smem_u32(smem);
    const int tid = threadIdx.x;
    const int warp = tid >> 5, lane = tid & 31;
    const int wm = warp & 3, wn = warp >> 2;
    const int n0 = t * 1024 + nblk * 128;
    const int nb = t * 8 + nblk;

    if (tid < 128)
        reinterpret_cast<float*>(smem + SMEM_SC)[tid] = scales[n0 + tid];
    if (tid == 0) {
#pragma unroll
        for (int s = 0; s < STAGES; s++) mbar_init(sb + 8u * s, 1);
    }
    __syncthreads();

    const unsigned char* aSrc = g_At + (((size_t)(t * 32 + mblk)) << 20);
    const unsigned char* bSrc = g_Wt + ((size_t)nb << 20);

    auto fill = [&](int s, int kt) {
        uint32_t mb = sb + 8u * s;
        uint32_t st = sb + SMEM_ST + s * STAGE_BYTES;
        mbar_expect_tx(mb, STAGE_BYTES);
        bulk_g2s(st,         aSrc + ((size_t)kt << 14), 16384, mb);
        bulk_g2s(st + 16384, bSrc + ((size_t)kt << 14), 16384, mb);
    };
    if (tid == 0) {
#pragma unroll
        for (int s = 0; s < STAGES; s++) fill(s, s);
    }

    // ldmatrix addressing (same fragment mapping validated in R1/R3)
    int aR[2];
#pragma unroll
    for (int ms = 0; ms < 2; ms++) aR[ms] = wm * 32 + ms * 16 + (lane & 15);
    const int aCadd = lane >> 4;
    int bR[4];
#pragma unroll
    for (int nq = 0; nq < 4; nq++)
        bR[nq] = wn * 64 + nq * 16 + (lane & 7) + ((lane >> 4) << 3);
    const int bCadd = (lane >> 3) & 1;

    float d[2][8][4];
#pragma unroll
    for (int a = 0; a < 2; a++)
#pragma unroll
        for (int b = 0; b < 8; b++)
#pragma unroll
            for (int c = 0; c < 4; c++) d[a][b][c] = 0.f;

    for (int kt = 0; kt < NKT; kt++) {
        const int s = kt & 3;
        mbar_wait(sb + 8u * s, (kt >> 2) & 1);
        const uint32_t st = sb + SMEM_ST + s * STAGE_BYTES;
#pragma unroll
        for (int ks = 0; ks < 4; ks++) {
            uint32_t a[2][4], bf[4][4];
#pragma unroll
            for (int ms = 0; ms < 2; ms++) {
                uint32_t off = aR[ms] * 128 +
                               (((ks * 2 + aCadd) ^ (aR[ms] & 7)) << 4);
                ldm_x4(a[ms], st + off);
            }
#pragma unroll
            for (int nq = 0; nq < 4; nq++) {
                uint32_t off = bR[nq] * 128 +
                               (((ks * 2 + bCadd) ^ (bR[nq] & 7)) << 4);
                ldm_x4(bf[nq], st + 16384 + off);
            }
#pragma unroll
            for (int ms = 0; ms < 2; ms++)
#pragma unroll
                for (int nq = 0; nq < 4; nq++) {
                    hmma(d[ms][nq * 2],     a[ms], bf[nq][0], bf[nq][1]);
                    hmma(d[ms][nq * 2 + 1], a[ms], bf[nq][2], bf[nq][3]);
                }
        }
        __syncthreads();
        if (tid == 0 && kt + STAGES < NKT) fill(s, kt + STAGES);
    }

    // epilogue: out = acc * scales[col] for gated rows
    const float* sSc = reinterpret_cast<const float*>(smem + SMEM_SC);
#pragma unroll
    for (int ms = 0; ms < 2; ms++) {
#pragma unroll
        for (int half = 0; half < 2; half++) {
            int gidx = mblk * 128 + wm * 32 + ms * 16 + (lane >> 2) + half * 8;
            if (gidx >= cnt) continue;
            int row = g_rows[t][gidx];
            float* orow = out + (size_t)row * NDIM + n0;
#pragma unroll
            for (int ns = 0; ns < 8; ns++) {
                int col = wn * 64 + ns * 8 + (lane & 3) * 2;
                float2 v;
                v.x = d[ms][ns][half * 2]     * sSc[col];
                v.y = d[ms][ns][half * 2 + 1] * sSc[col + 1];
                *reinterpret_cast<float2*>(orow + col) = v;
            }
        }
    }
}

// ------------------------------ launch --------------------------------------

extern "C" void kernel_launch(void* const* d_in, const int* in_sizes, int n_in,
                              void* d_out, int out_size) {
    const float* x      = (const float*)d_in[0];
    const int*   gate   = (const int*)d_in[1];
    const float* weight = (const float*)d_in[2];
    const float* scales = (const float*)d_in[3];
    float* out = (float*)d_out;

    cudaFuncSetAttribute(trix_hmma,
                         cudaFuncAttributeMaxDynamicSharedMemorySize, SMEM_TOTAL);

    zero_ungated<<<MDIM * 4, 256>>>(gate, out);
    quant_x<<<(int)((size_t)MDIM * KDIM / 8 / 256), 256>>>(x);
    sign_w<<<(int)((size_t)NDIM * KDIM / 8 / 256), 256>>>(weight);
    compact_gate<<<MDIM / 512, 512>>>(gate);
    gather_a<<<dim3(32, 4), 256>>>();
    trix_hmma<<<dim3(8, 32, 4), 256, SMEM_TOTAL>>>(scales, out);
}

// round 5
// speedup vs baseline: 4.5993x; 1.3372x over previous
#include <cuda_runtime.h>
#include <cuda_fp16.h>
#include <cstdint>

// ---------------------------------------------------------------------------
// TriXLinear (sm_103 baseline PTX; tensor path = mma.sync m16n8k16 f16).
//   out = (x @ sign(W)^T) * scales * gate_mask
// x -> fp16 (norm rel err ~2.1e-4), W -> +-1 fp16 (exact). Gated-row GEMM.
// GEMM: 128-thread CTA, warp tile 64x64, block 128x128, BK=64,
// 3-stage cp.async.bulk + full/empty mbarrier pipeline, 2 CTAs/SM.
// ---------------------------------------------------------------------------

#define MDIM 4096
#define NDIM 4096
#define KDIM 4096

#define NKT 64                         // K stages (64 fp16 = 128B rows)
#define STAGES 3
#define STAGE_BYTES 32768              // A 16K + B 16K
#define SMEM_SC 64                     // scales cache at byte 64 (512B)
#define SMEM_ST 1024
#define SMEM_TOTAL (SMEM_ST + STAGES * STAGE_BYTES)   // 99328 -> 2 CTAs/SM
// mbarriers: full[s] at sb+8s, empty[s] at sb+24+8s  (s = 0..2); bytes 0..48

// ------------------------------- scratch -----------------------------------
__device__ __align__(1024) unsigned char g_Wt[(size_t)32 * 1024 * 1024];
__device__ __align__(1024) unsigned char g_At[(size_t)128 * 1024 * 1024];
__device__ int g_cnt[4];
__device__ int g_rows[4][MDIM];

// ------------------------------ PTX helpers --------------------------------
__device__ __forceinline__ uint32_t smem_u32(const void* p) {
    uint32_t a;
    asm("{ .reg .u64 t; cvta.to.shared.u64 t, %1; cvt.u32.u64 %0, t; }"
        : "=r"(a) : "l"(p));
    return a;
}
__device__ __forceinline__ uint32_t elect_one() {
    uint32_t p;
    asm volatile("{ .reg .pred p; elect.sync _|p, 0xFFFFFFFF; selp.b32 %0,1,0,p; }"
                 : "=r"(p));
    return p;
}
__device__ __forceinline__ void mbar_init(uint32_t mb, uint32_t cnt) {
    asm volatile("mbarrier.init.shared.b64 [%0], %1;" :: "r"(mb), "r"(cnt) : "memory");
}
__device__ __forceinline__ void mbar_expect_tx(uint32_t mb, uint32_t bytes) {
    asm volatile("mbarrier.arrive.expect_tx.shared.b64 _, [%0], %1;"
                 :: "r"(mb), "r"(bytes) : "memory");
}
__device__ __forceinline__ void mbar_arrive(uint32_t mb) {
    asm volatile("mbarrier.arrive.shared.b64 _, [%0];" :: "r"(mb) : "memory");
}
__device__ __forceinline__ void mbar_wait(uint32_t mb, uint32_t parity) {
    asm volatile(
        "{\n\t.reg .pred P;\n\t"
        "WL_%=:\n\t"
        "mbarrier.try_wait.parity.acquire.cta.shared::cta.b64 P, [%0], %1, 0x989680;\n\t"
        "@P bra.uni WD_%=;\n\t"
        "bra.uni WL_%=;\n\t"
        "WD_%=:\n\t}"
        :: "r"(mb), "r"(parity) : "memory");
}
__device__ __forceinline__ void bulk_g2s(uint32_t dst, const void* src,
                                         uint32_t bytes, uint32_t mb) {
    asm volatile(
        "cp.async.bulk.shared::cta.global.mbarrier::complete_tx::bytes "
        "[%0], [%1], %2, [%3];"
        :: "r"(dst), "l"(src), "r"(bytes), "r"(mb) : "memory");
}
__device__ __forceinline__ void ldm_x4(uint32_t* r, uint32_t addr) {
    asm volatile("ldmatrix.sync.aligned.m8n8.x4.shared.b16 {%0,%1,%2,%3}, [%4];"
                 : "=r"(r[0]), "=r"(r[1]), "=r"(r[2]), "=r"(r[3]) : "r"(addr));
}
__device__ __forceinline__ void hmma(float* c, const uint32_t* a,
                                     uint32_t b0, uint32_t b1) {
    asm volatile(
        "mma.sync.aligned.m16n8k16.row.col.f32.f16.f16.f32 "
        "{%0,%1,%2,%3}, {%4,%5,%6,%7}, {%8,%9}, {%0,%1,%2,%3};"
        : "+f"(c[0]), "+f"(c[1]), "+f"(c[2]), "+f"(c[3])
        : "r"(a[0]), "r"(a[1]), "r"(a[2]), "r"(a[3]), "r"(b0), "r"(b1));
}

// ------------------------------ prep kernels --------------------------------

// zero ungated (row, tile) output blocks; block 0 also zeroes g_cnt
__global__ void zero_ungated(const int* __restrict__ gate,
                             float* __restrict__ out) {
    int bid = blockIdx.x;            // 16384 = 4096 rows * 4 tiles
    if (bid == 0 && threadIdx.x < 4) g_cnt[threadIdx.x] = 0;
    int r = bid >> 2, t = bid & 3;
    if (gate[r * 4 + t] != 0) return;
    float4 z = {0.f, 0.f, 0.f, 0.f};
    reinterpret_cast<float4*>(out + (size_t)r * NDIM + t * 1024)[threadIdx.x] = z;
}

// sign(W) -> fp16, tiled [nb][kblk] 16KB stages; row r, 16B chunk c at c^(r&7)
__global__ void sign_w(const float* __restrict__ w) {
    size_t idx = (size_t)blockIdx.x * blockDim.x + threadIdx.x;  // *8 elems
    int row = (int)(idx >> 9);
    int k0  = ((int)idx & 511) * 8;
    const float4* p = reinterpret_cast<const float4*>(w + (size_t)row * KDIM + k0);
    float4 v0 = p[0], v1 = p[1];
    float f[8] = {v0.x, v0.y, v0.z, v0.w, v1.x, v1.y, v1.z, v1.w};
    __half s[8];
#pragma unroll
    for (int j = 0; j < 8; j++)
        s[j] = __float2half_rn((f[j] > 0.f) ? 1.f : ((f[j] < 0.f) ? -1.f : 0.f));
    int nb = row >> 7, r = row & 127, kblk = k0 >> 6;
    int c = (k0 & 63) >> 3;
    size_t off = (((size_t)(nb * 64 + kblk)) << 14) +
                 (size_t)r * 128 + ((size_t)(c ^ (r & 7)) << 4);
    *reinterpret_cast<uint4*>(g_Wt + off) = *reinterpret_cast<uint4*>(s);
}

// gated row compaction (order irrelevant)
__global__ void compact_gate(const int* __restrict__ gate) {
    int r = blockIdx.x * blockDim.x + threadIdx.x;
    if (r >= MDIM) return;
#pragma unroll
    for (int t = 0; t < 4; t++) {
        if (gate[r * 4 + t] != 0) {
            int pos = atomicAdd(&g_cnt[t], 1);
            g_rows[t][pos] = r;
        }
    }
}

// fused gather+quant: read gated x rows (f32), write fp16 swizzled A tiles.
// chunk (t, mblk) = 1MB = [kblk 0..63] x (128 rows x 128B), chunk c at c^(r&7).
__global__ __launch_bounds__(256) void gather_quant(const float* __restrict__ x) {
    int mblk = blockIdx.x, t = blockIdx.y;
    int cnt = g_cnt[t];
    if (mblk * 128 >= cnt) return;
    __shared__ int srow[128];
    int tid = threadIdx.x;
    if (tid < 128) {
        int gidx = mblk * 128 + tid;
        srow[tid] = (gidx < cnt) ? g_rows[t][gidx] : g_rows[t][0];
    }
    __syncthreads();
    size_t base = ((size_t)(t * 32 + mblk)) << 20;
    int r = tid >> 3, c = tid & 7;            // 32 rows x 8 chunks / pass
#pragma unroll 1
    for (int kblk = 0; kblk < 64; kblk++) {
        size_t db = base + ((size_t)kblk << 14);
#pragma unroll
        for (int rp = 0; rp < 4; rp++) {
            int rr = r + rp * 32;
            const float4* src = reinterpret_cast<const float4*>(
                x + (size_t)srow[rr] * KDIM + kblk * 64 + c * 8);
            float4 v0 = src[0], v1 = src[1];
            __half h[8];
            h[0] = __float2half_rn(v0.x); h[1] = __float2half_rn(v0.y);
            h[2] = __float2half_rn(v0.z); h[3] = __float2half_rn(v0.w);
            h[4] = __float2half_rn(v1.x); h[5] = __float2half_rn(v1.y);
            h[6] = __float2half_rn(v1.z); h[7] = __float2half_rn(v1.w);
            size_t dd = db + (size_t)rr * 128 + ((size_t)(c ^ (rr & 7)) << 4);
            *reinterpret_cast<uint4*>(g_At + dd) = *reinterpret_cast<uint4*>(h);
        }
    }
}

// ------------------------------ GEMM kernel ---------------------------------
// grid (8 nblk, 32 mblk, 4 t), 128 threads, warp grid 2(M) x 2(N), warp 64x64.

__global__ __launch_bounds__(128, 2) void trix_hmma(
    const float* __restrict__ scales,
    float* __restrict__ out) {
    const int t = blockIdx.z, mblk = blockIdx.y, nblk = blockIdx.x;
    const int cnt = g_cnt[t];
    if (mblk * 128 >= cnt) return;

    extern __shared__ char smem[];
    const uint32_t sb = smem_u32(smem);
    const int tid = threadIdx.x;
    const int warp = tid >> 5, lane = tid & 31;
    const int wm = warp >> 1, wn = warp & 1;
    const int n0 = t * 1024 + nblk * 128;
    const int nb = t * 8 + nblk;

    reinterpret_cast<float*>(smem + SMEM_SC)[tid] = scales[n0 + tid];
    if (tid == 0) {
#pragma unroll
        for (int s = 0; s < STAGES; s++) {
            mbar_init(sb + 8u * s, 1);        // full: TMA tx
            mbar_init(sb + 24u + 8u * s, 4);  // empty: 4 warp arrivals
        }
    }
    __syncthreads();

    const unsigned char* aSrc = g_At + (((size_t)(t * 32 + mblk)) << 20);
    const unsigned char* bSrc = g_Wt + ((size_t)nb << 20);

    auto fill = [&](int s, int kt) {
        uint32_t mb = sb + 8u * s;
        uint32_t st = sb + SMEM_ST + s * STAGE_BYTES;
        mbar_expect_tx(mb, STAGE_BYTES);
        bulk_g2s(st,         aSrc + ((size_t)kt << 14), 16384, mb);
        bulk_g2s(st + 16384, bSrc + ((size_t)kt << 14), 16384, mb);
    };
    const bool prod = (warp == 0) && elect_one();
    if (prod) {
#pragma unroll
        for (int s = 0; s < STAGES; s++) fill(s, s);
    }

    // ldmatrix addressing
    int aR[4], bR[4];
#pragma unroll
    for (int ms = 0; ms < 4; ms++) aR[ms] = wm * 64 + ms * 16 + (lane & 15);
    const int aCadd = lane >> 4;
#pragma unroll
    for (int nq = 0; nq < 4; nq++)
        bR[nq] = wn * 64 + nq * 16 + (lane & 7) + ((lane >> 4) << 3);
    const int bCadd = (lane >> 3) & 1;

    float d[4][8][4];
#pragma unroll
    for (int a = 0; a < 4; a++)
#pragma unroll
        for (int b = 0; b < 8; b++)
#pragma unroll
            for (int c = 0; c < 4; c++) d[a][b][c] = 0.f;

    for (int kt = 0; kt < NKT; kt++) {
        const int s = kt % 3;
        const uint32_t ph = (uint32_t)((kt / 3) & 1);
        mbar_wait(sb + 8u * s, ph);                       // data ready
        const uint32_t st = sb + SMEM_ST + s * STAGE_BYTES;
#pragma unroll
        for (int ks = 0; ks < 4; ks++) {
            uint32_t a[4][4], bf[4][4];
#pragma unroll
            for (int ms = 0; ms < 4; ms++) {
                uint32_t off = aR[ms] * 128 +
                               (((ks * 2 + aCadd) ^ (aR[ms] & 7)) << 4);
                ldm_x4(a[ms], st + off);
            }
#pragma unroll
            for (int nq = 0; nq < 4; nq++) {
                uint32_t off = bR[nq] * 128 +
                               (((ks * 2 + bCadd) ^ (bR[nq] & 7)) << 4);
                ldm_x4(bf[nq], st + 16384 + off);
            }
#pragma unroll
            for (int ms = 0; ms < 4; ms++)
#pragma unroll
                for (int nq = 0; nq < 4; nq++) {
                    hmma(d[ms][nq * 2],     a[ms], bf[nq][0], bf[nq][1]);
                    hmma(d[ms][nq * 2 + 1], a[ms], bf[nq][2], bf[nq][3]);
                }
        }
        if (elect_one()) mbar_arrive(sb + 24u + 8u * s);  // warp consumed
        if (prod && kt + STAGES < NKT) {
            mbar_wait(sb + 24u + 8u * s, ph);             // all 4 consumed
            fill(s, kt + STAGES);
        }
    }

    // epilogue: out = acc * scales[col] for gated rows
    const float* sSc = reinterpret_cast<const float*>(smem + SMEM_SC);
#pragma unroll
    for (int ms = 0; ms < 4; ms++) {
#pragma unroll
        for (int half = 0; half < 2; half++) {
            int gidx = mblk * 128 + wm * 64 + ms * 16 + (lane >> 2) + half * 8;
            if (gidx >= cnt) continue;
            int row = g_rows[t][gidx];
            float* orow = out + (size_t)row * NDIM + n0;
#pragma unroll
            for (int ns = 0; ns < 8; ns++) {
                int col = wn * 64 + ns * 8 + (lane & 3) * 2;
                float2 v;
                v.x = d[ms][ns][half * 2]     * sSc[col];
                v.y = d[ms][ns][half * 2 + 1] * sSc[col + 1];
                *reinterpret_cast<float2*>(orow + col) = v;
            }
        }
    }
}

// ------------------------------ launch --------------------------------------

extern "C" void kernel_launch(void* const* d_in, const int* in_sizes, int n_in,
                              void* d_out, int out_size) {
    const float* x      = (const float*)d_in[0];
    const int*   gate   = (const int*)d_in[1];
    const float* weight = (const float*)d_in[2];
    const float* scales = (const float*)d_in[3];
    float* out = (float*)d_out;

    cudaFuncSetAttribute(trix_hmma,
                         cudaFuncAttributeMaxDynamicSharedMemorySize, SMEM_TOTAL);

    zero_ungated<<<MDIM * 4, 256>>>(gate, out);
    sign_w<<<(int)((size_t)NDIM * KDIM / 8 / 256), 256>>>(weight);
    compact_gate<<<MDIM / 512, 512>>>(gate);
    gather_quant<<<dim3(32, 4), 256>>>(x);
    trix_hmma<<<dim3(8, 32, 4), 128, SMEM_TOTAL>>>(scales, out);
}

// round 6
// speedup vs baseline: 5.8476x; 1.2714x over previous
#include <cuda_runtime.h>
#include <cuda_fp16.h>
#include <cstdint>

// ---------------------------------------------------------------------------
// TriXLinear (sm_103 baseline PTX; tensor path = mma.sync m16n8k16 f16).
//   out = (x @ sign(W)^T) * scales * gate_mask
// x -> fp16 (norm rel err ~2.1e-4), W -> +-1 fp16 (exact). Gated-row GEMM.
// GEMM: 128-thread CTA, warp tile 64x64, block 128x128, BK=64,
// 3-stage cp.async.bulk + full/empty mbarrier pipeline, 2 CTAs/SM.
// R6: gather_quant parallelized over K (8 kgroups) to fix MLP starvation.
// ---------------------------------------------------------------------------

#define MDIM 4096
#define NDIM 4096
#define KDIM 4096

#define NKT 64                         // K stages (64 fp16 = 128B rows)
#define STAGES 3
#define STAGE_BYTES 32768              // A 16K + B 16K
#define SMEM_SC 64                     // scales cache at byte 64 (512B)
#define SMEM_ST 1024
#define SMEM_TOTAL (SMEM_ST + STAGES * STAGE_BYTES)   // 99328 -> 2 CTAs/SM
// mbarriers: full[s] at sb+8s, empty[s] at sb+24+8s  (s = 0..2)

// ------------------------------- scratch -----------------------------------
__device__ __align__(1024) unsigned char g_Wt[(size_t)32 * 1024 * 1024];
__device__ __align__(1024) unsigned char g_At[(size_t)128 * 1024 * 1024];
__device__ int g_cnt[4];
__device__ int g_rows[4][MDIM];

// ------------------------------ PTX helpers --------------------------------
__device__ __forceinline__ uint32_t smem_u32(const void* p) {
    uint32_t a;
    asm("{ .reg .u64 t; cvta.to.shared.u64 t, %1; cvt.u32.u64 %0, t; }"
        : "=r"(a) : "l"(p));
    return a;
}
__device__ __forceinline__ uint32_t elect_one() {
    uint32_t p;
    asm volatile("{ .reg .pred p; elect.sync _|p, 0xFFFFFFFF; selp.b32 %0,1,0,p; }"
                 : "=r"(p));
    return p;
}
__device__ __forceinline__ void mbar_init(uint32_t mb, uint32_t cnt) {
    asm volatile("mbarrier.init.shared.b64 [%0], %1;" :: "r"(mb), "r"(cnt) : "memory");
}
__device__ __forceinline__ void mbar_expect_tx(uint32_t mb, uint32_t bytes) {
    asm volatile("mbarrier.arrive.expect_tx.shared.b64 _, [%0], %1;"
                 :: "r"(mb), "r"(bytes) : "memory");
}
__device__ __forceinline__ void mbar_arrive(uint32_t mb) {
    asm volatile("mbarrier.arrive.shared.b64 _, [%0];" :: "r"(mb) : "memory");
}
__device__ __forceinline__ void mbar_wait(uint32_t mb, uint32_t parity) {
    asm volatile(
        "{\n\t.reg .pred P;\n\t"
        "WL_%=:\n\t"
        "mbarrier.try_wait.parity.acquire.cta.shared::cta.b64 P, [%0], %1, 0x989680;\n\t"
        "@P bra.uni WD_%=;\n\t"
        "bra.uni WL_%=;\n\t"
        "WD_%=:\n\t}"
        :: "r"(mb), "r"(parity) : "memory");
}
__device__ __forceinline__ void bulk_g2s(uint32_t dst, const void* src,
                                         uint32_t bytes, uint32_t mb) {
    asm volatile(
        "cp.async.bulk.shared::cta.global.mbarrier::complete_tx::bytes "
        "[%0], [%1], %2, [%3];"
        :: "r"(dst), "l"(src), "r"(bytes), "r"(mb) : "memory");
}
__device__ __forceinline__ void ldm_x4(uint32_t* r, uint32_t addr) {
    asm volatile("ldmatrix.sync.aligned.m8n8.x4.shared.b16 {%0,%1,%2,%3}, [%4];"
                 : "=r"(r[0]), "=r"(r[1]), "=r"(r[2]), "=r"(r[3]) : "r"(addr));
}
__device__ __forceinline__ void hmma(float* c, const uint32_t* a,
                                     uint32_t b0, uint32_t b1) {
    asm volatile(
        "mma.sync.aligned.m16n8k16.row.col.f32.f16.f16.f32 "
        "{%0,%1,%2,%3}, {%4,%5,%6,%7}, {%8,%9}, {%0,%1,%2,%3};"
        : "+f"(c[0]), "+f"(c[1]), "+f"(c[2]), "+f"(c[3])
        : "r"(a[0]), "r"(a[1]), "r"(a[2]), "r"(a[3]), "r"(b0), "r"(b1));
}

// ------------------------------ prep kernels --------------------------------

// zero ungated (row, tile) output blocks; block 0 also zeroes g_cnt
__global__ void zero_ungated(const int* __restrict__ gate,
                             float* __restrict__ out) {
    int bid = blockIdx.x;            // 16384 = 4096 rows * 4 tiles
    if (bid == 0 && threadIdx.x < 4) g_cnt[threadIdx.x] = 0;
    int r = bid >> 2, t = bid & 3;
    if (gate[r * 4 + t] != 0) return;
    float4 z = {0.f, 0.f, 0.f, 0.f};
    reinterpret_cast<float4*>(out + (size_t)r * NDIM + t * 1024)[threadIdx.x] = z;
}

// sign(W) -> fp16, tiled [nb][kblk] 16KB stages; row r, 16B chunk c at c^(r&7)
__global__ void sign_w(const float* __restrict__ w) {
    size_t idx = (size_t)blockIdx.x * blockDim.x + threadIdx.x;  // *8 elems
    int row = (int)(idx >> 9);
    int k0  = ((int)idx & 511) * 8;
    const float4* p = reinterpret_cast<const float4*>(w + (size_t)row * KDIM + k0);
    float4 v0 = p[0], v1 = p[1];
    float f[8] = {v0.x, v0.y, v0.z, v0.w, v1.x, v1.y, v1.z, v1.w};
    __half s[8];
#pragma unroll
    for (int j = 0; j < 8; j++)
        s[j] = __float2half_rn((f[j] > 0.f) ? 1.f : ((f[j] < 0.f) ? -1.f : 0.f));
    int nb = row >> 7, r = row & 127, kblk = k0 >> 6;
    int c = (k0 & 63) >> 3;
    size_t off = (((size_t)(nb * 64 + kblk)) << 14) +
                 (size_t)r * 128 + ((size_t)(c ^ (r & 7)) << 4);
    *reinterpret_cast<uint4*>(g_Wt + off) = *reinterpret_cast<uint4*>(s);
}

// gated row compaction (order irrelevant)
__global__ void compact_gate(const int* __restrict__ gate) {
    int r = blockIdx.x * blockDim.x + threadIdx.x;
    if (r >= MDIM) return;
#pragma unroll
    for (int t = 0; t < 4; t++) {
        if (gate[r * 4 + t] != 0) {
            int pos = atomicAdd(&g_cnt[t], 1);
            g_rows[t][pos] = r;
        }
    }
}

// fused gather+quant: read gated x rows (f32), write fp16 swizzled A tiles.
// chunk (t, mblk) = 1MB = [kblk 0..63] x (128 rows x 128B), chunk c at c^(r&7).
// R6: grid (32 mblk, 4 t, 8 kg) — each block does 8 kblks for full MLP.
__global__ __launch_bounds__(256) void gather_quant(const float* __restrict__ x) {
    int mblk = blockIdx.x, t = blockIdx.y, kg = blockIdx.z;
    int cnt = g_cnt[t];
    if (mblk * 128 >= cnt) return;
    __shared__ int srow[128];
    int tid = threadIdx.x;
    if (tid < 128) {
        int gidx = mblk * 128 + tid;
        srow[tid] = (gidx < cnt) ? g_rows[t][gidx] : g_rows[t][0];
    }
    __syncthreads();
    size_t base = ((size_t)(t * 32 + mblk)) << 20;
    int r = tid >> 3, c = tid & 7;            // 32 rows x 8 chunks / pass
#pragma unroll
    for (int kb = 0; kb < 8; kb++) {
        int kblk = kg * 8 + kb;
        size_t db = base + ((size_t)kblk << 14);
#pragma unroll
        for (int rp = 0; rp < 4; rp++) {
            int rr = r + rp * 32;
            const float4* src = reinterpret_cast<const float4*>(
                x + (size_t)srow[rr] * KDIM + kblk * 64 + c * 8);
            float4 v0 = src[0], v1 = src[1];
            __half h[8];
            h[0] = __float2half_rn(v0.x); h[1] = __float2half_rn(v0.y);
            h[2] = __float2half_rn(v0.z); h[3] = __float2half_rn(v0.w);
            h[4] = __float2half_rn(v1.x); h[5] = __float2half_rn(v1.y);
            h[6] = __float2half_rn(v1.z); h[7] = __float2half_rn(v1.w);
            size_t dd = db + (size_t)rr * 128 + ((size_t)(c ^ (rr & 7)) << 4);
            *reinterpret_cast<uint4*>(g_At + dd) = *reinterpret_cast<uint4*>(h);
        }
    }
}

// ------------------------------ GEMM kernel ---------------------------------
// grid (8 nblk, 32 mblk, 4 t), 128 threads, warp grid 2(M) x 2(N), warp 64x64.

__global__ __launch_bounds__(128, 2) void trix_hmma(
    const float* __restrict__ scales,
    float* __restrict__ out) {
    const int t = blockIdx.z, mblk = blockIdx.y, nblk = blockIdx.x;
    const int cnt = g_cnt[t];
    if (mblk * 128 >= cnt) return;

    extern __shared__ char smem[];
    const uint32_t sb = smem_u32(smem);
    const int tid = threadIdx.x;
    const int warp = tid >> 5, lane = tid & 31;
    const int wm = warp >> 1, wn = warp & 1;
    const int n0 = t * 1024 + nblk * 128;
    const int nb = t * 8 + nblk;

    reinterpret_cast<float*>(smem + SMEM_SC)[tid] = scales[n0 + tid];
    if (tid == 0) {
#pragma unroll
        for (int s = 0; s < STAGES; s++) {
            mbar_init(sb + 8u * s, 1);        // full: TMA tx
            mbar_init(sb + 24u + 8u * s, 4);  // empty: 4 warp arrivals
        }
    }
    __syncthreads();

    const unsigned char* aSrc = g_At + (((size_t)(t * 32 + mblk)) << 20);
    const unsigned char* bSrc = g_Wt + ((size_t)nb << 20);

    auto fill = [&](int s, int kt) {
        uint32_t mb = sb + 8u * s;
        uint32_t st = sb + SMEM_ST + s * STAGE_BYTES;
        mbar_expect_tx(mb, STAGE_BYTES);
        bulk_g2s(st,         aSrc + ((size_t)kt << 14), 16384, mb);
        bulk_g2s(st + 16384, bSrc + ((size_t)kt << 14), 16384, mb);
    };
    const bool prod = (warp == 0) && elect_one();
    if (prod) {
#pragma unroll
        for (int s = 0; s < STAGES; s++) fill(s, s);
    }

    // ldmatrix addressing
    int aR[4], bR[4];
#pragma unroll
    for (int ms = 0; ms < 4; ms++) aR[ms] = wm * 64 + ms * 16 + (lane & 15);
    const int aCadd = lane >> 4;
#pragma unroll
    for (int nq = 0; nq < 4; nq++)
        bR[nq] = wn * 64 + nq * 16 + (lane & 7) + ((lane >> 4) << 3);
    const int bCadd = (lane >> 3) & 1;

    float d[4][8][4];
#pragma unroll
    for (int a = 0; a < 4; a++)
#pragma unroll
        for (int b = 0; b < 8; b++)
#pragma unroll
            for (int c = 0; c < 4; c++) d[a][b][c] = 0.f;

    for (int kt = 0; kt < NKT; kt++) {
        const int s = kt % 3;
        const uint32_t ph = (uint32_t)((kt / 3) & 1);
        mbar_wait(sb + 8u * s, ph);                       // data ready
        const uint32_t st = sb + SMEM_ST + s * STAGE_BYTES;
#pragma unroll
        for (int ks = 0; ks < 4; ks++) {
            uint32_t a[4][4], bf[4][4];
#pragma unroll
            for (int ms = 0; ms < 4; ms++) {
                uint32_t off = aR[ms] * 128 +
                               (((ks * 2 + aCadd) ^ (aR[ms] & 7)) << 4);
                ldm_x4(a[ms], st + off);
            }
#pragma unroll
            for (int nq = 0; nq < 4; nq++) {
                uint32_t off = bR[nq] * 128 +
                               (((ks * 2 + bCadd) ^ (bR[nq] & 7)) << 4);
                ldm_x4(bf[nq], st + 16384 + off);
            }
#pragma unroll
            for (int ms = 0; ms < 4; ms++)
#pragma unroll
                for (int nq = 0; nq < 4; nq++) {
                    hmma(d[ms][nq * 2],     a[ms], bf[nq][0], bf[nq][1]);
                    hmma(d[ms][nq * 2 + 1], a[ms], bf[nq][2], bf[nq][3]);
                }
        }
        if (elect_one()) mbar_arrive(sb + 24u + 8u * s);  // warp consumed
        if (prod && kt + STAGES < NKT) {
            mbar_wait(sb + 24u + 8u * s, ph);             // all 4 consumed
            fill(s, kt + STAGES);
        }
    }

    // epilogue: out = acc * scales[col] for gated rows
    const float* sSc = reinterpret_cast<const float*>(smem + SMEM_SC);
#pragma unroll
    for (int ms = 0; ms < 4; ms++) {
#pragma unroll
        for (int half = 0; half < 2; half++) {
            int gidx = mblk * 128 + wm * 64 + ms * 16 + (lane >> 2) + half * 8;
            if (gidx >= cnt) continue;
            int row = g_rows[t][gidx];
            float* orow = out + (size_t)row * NDIM + n0;
#pragma unroll
            for (int ns = 0; ns < 8; ns++) {
                int col = wn * 64 + ns * 8 + (lane & 3) * 2;
                float2 v;
                v.x = d[ms][ns][half * 2]     * sSc[col];
                v.y = d[ms][ns][half * 2 + 1] * sSc[col + 1];
                *reinterpret_cast<float2*>(orow + col) = v;
            }
        }
    }
}

// ------------------------------ launch --------------------------------------

extern "C" void kernel_launch(void* const* d_in, const int* in_sizes, int n_in,
                              void* d_out, int out_size) {
    const float* x      = (const float*)d_in[0];
    const int*   gate   = (const int*)d_in[1];
    const float* weight = (const float*)d_in[2];
    const float* scales = (const float*)d_in[3];
    float* out = (float*)d_out;

    cudaFuncSetAttribute(trix_hmma,
                         cudaFuncAttributeMaxDynamicSharedMemorySize, SMEM_TOTAL);

    zero_ungated<<<MDIM * 4, 256>>>(gate, out);
    sign_w<<<(int)((size_t)NDIM * KDIM / 8 / 256), 256>>>(weight);
    compact_gate<<<MDIM / 512, 512>>>(gate);
    gather_quant<<<dim3(32, 4, 8), 256>>>(x);
    trix_hmma<<<dim3(8, 32, 4), 128, SMEM_TOTAL>>>(scales, out);
}